// round 14
// baseline (speedup 1.0000x reference)
#include <cuda_runtime.h>
#include <cuda_fp16.h>
#include <cstdint>

#define DFEAT 64
#define NREL 16
#define NCOLS 1088           // (NREL+1)*64
#define RELCOLS 1024         // NREL*64 halves per Yh row
#define NNODE_MAX 100000
#define EDGE_MAX  1500000
#define NBLK_MAX  128

typedef unsigned long long u64;

// ---------------------------------------------------------------------------
// Scratch (allocation-free, __device__ globals)
// ---------------------------------------------------------------------------
__device__ __half   g_Yh[(size_t)NNODE_MAX * RELCOLS];  // ~205 MB fp16 messages
__device__ float    g_h[(size_t)NNODE_MAX * DFEAT];
__device__ __half   g_Xhi[(size_t)NNODE_MAX * DFEAT];
__device__ __half   g_Xlo[(size_t)NNODE_MAX * DFEAT];
__device__ __half   g_Bhi[2 * NCOLS * DFEAT];           // double-buffered (layer 1/2)
__device__ __half   g_Blo[2 * NCOLS * DFEAT];
__device__ uint8_t  g_used[NREL * NNODE_MAX];           // (rel,src) has >=1 edge
// CSR
__device__ int      g_cnt[NNODE_MAX];
__device__ int      g_indptr[NNODE_MAX + 1];
__device__ int      g_cursor[NNODE_MAX];
__device__ int      g_bsum[NBLK_MAX];
__device__ uint32_t g_edata[EDGE_MAX];   // src | ty<<20

// ---------------------------------------------------------------------------
__device__ __forceinline__ uint32_t smem_to_u32(const void* p) {
    uint32_t a;
    asm("{ .reg .u64 t; cvta.to.shared.u64 t, %1; cvt.u32.u64 %0, t; }" : "=r"(a) : "l"(p));
    return a;
}
__device__ __forceinline__ void ldsm4(uint32_t* r, uint32_t a) {
    asm volatile("ldmatrix.sync.aligned.m8n8.x4.shared.b16 {%0,%1,%2,%3}, [%4];"
                 : "=r"(r[0]), "=r"(r[1]), "=r"(r[2]), "=r"(r[3]) : "r"(a));
}
__device__ __forceinline__ void mma_fp16(float* d, const uint32_t* a, const uint32_t* b) {
    asm volatile("mma.sync.aligned.m16n8k16.row.col.f32.f16.f16.f32 "
                 "{%0,%1,%2,%3}, {%4,%5,%6,%7}, {%8,%9}, {%0,%1,%2,%3};"
                 : "+f"(d[0]), "+f"(d[1]), "+f"(d[2]), "+f"(d[3])
                 : "r"(a[0]), "r"(a[1]), "r"(a[2]), "r"(a[3]), "r"(b[0]), "r"(b[1]));
}

// ---------------------------------------------------------------------------
// CSR build kernels
// ---------------------------------------------------------------------------
__global__ void hist_k(const int* __restrict__ ei, int E) {
    int e = blockIdx.x * blockDim.x + threadIdx.x;
    if (e >= E) return;
    atomicAdd(&g_cnt[ei[E + e]], 1);
}
__global__ void mark_k(const int* __restrict__ ei, const int* __restrict__ et,
                       int E, int N) {
    int e = blockIdx.x * blockDim.x + threadIdx.x;
    if (e >= E) return;
    g_used[(size_t)et[e] * N + ei[e]] = 1;   // races benign: all write 1
}
__global__ void scan1(int N) {
    __shared__ int sh[1024];
    int gid = blockIdx.x * 1024 + threadIdx.x;
    int v = (gid < N) ? g_cnt[gid] : 0;
    sh[threadIdx.x] = v;
    __syncthreads();
    for (int off = 1; off < 1024; off <<= 1) {
        int t = (threadIdx.x >= off) ? sh[threadIdx.x - off] : 0;
        __syncthreads();
        sh[threadIdx.x] += t;
        __syncthreads();
    }
    if (gid < N) g_indptr[gid] = sh[threadIdx.x] - v;
    if (threadIdx.x == 1023) g_bsum[blockIdx.x] = sh[1023];
}
__global__ void scan2(int nb) {
    __shared__ int sh[NBLK_MAX];
    int t = threadIdx.x;
    int v = (t < nb) ? g_bsum[t] : 0;
    sh[t] = v;
    __syncthreads();
    for (int off = 1; off < NBLK_MAX; off <<= 1) {
        int a = (t >= off) ? sh[t - off] : 0;
        __syncthreads();
        sh[t] += a;
        __syncthreads();
    }
    if (t < nb) g_bsum[t] = sh[t] - v;
}
__global__ void scan3(int N, int E) {
    int gid = blockIdx.x * 1024 + threadIdx.x;
    if (gid < N) {
        int v = g_indptr[gid] + g_bsum[blockIdx.x];
        g_indptr[gid] = v;
        g_cursor[gid] = v;
    }
    if (gid == 0) g_indptr[N] = E;
}
__global__ void fill_k(const int* __restrict__ ei, const int* __restrict__ et, int E) {
    int e = blockIdx.x * blockDim.x + threadIdx.x;
    if (e >= E) return;
    int src = ei[e];
    int dst = ei[E + e];
    int ty  = et[e];
    int pos = atomicAdd(&g_cursor[dst], 1);
    g_edata[pos] = (uint32_t)src | ((uint32_t)ty << 20);
}

// ---------------------------------------------------------------------------
// fp16 hi/lo conversion (layer-1 input only)
// ---------------------------------------------------------------------------
__global__ void conv_fp16(const float* __restrict__ src, int total4) {
    int idx4 = blockIdx.x * blockDim.x + threadIdx.x;
    if (idx4 >= total4) return;
    float4 v = *(const float4*)(src + (size_t)idx4 * 4);
    float f[4] = {v.x, v.y, v.z, v.w};
    union { __half b[4]; uint2 u; } hi, lo;
#pragma unroll
    for (int i = 0; i < 4; i++) {
        hi.b[i] = __float2half_rn(f[i]);
        lo.b[i] = __float2half_rn(f[i] - __half2float(hi.b[i]));
    }
    *(uint2*)(g_Xhi + (size_t)idx4 * 4) = hi.u;
    *(uint2*)(g_Xlo + (size_t)idx4 * 4) = lo.u;
}

// ---------------------------------------------------------------------------
// Pack B[c][k] = Wcat[k][c] (fp16 hi/lo) into buffer `buf`
// ---------------------------------------------------------------------------
__global__ void pack_wb(const float* __restrict__ W, const float* __restrict__ sw, int buf) {
    int idx = blockIdx.x * blockDim.x + threadIdx.x;
    if (idx >= NCOLS * DFEAT) return;
    int c = idx / DFEAT;
    int k = idx - c * DFEAT;
    float v;
    if (c < DFEAT) {
        v = sw[k * DFEAT + c];
    } else {
        int rc = c - DFEAT;
        int r = rc >> 6, j = rc & 63;
        v = W[r * DFEAT * DFEAT + k * DFEAT + j];
    }
    __half hi = __float2half_rn(v);
    __half lo = __float2half_rn(v - __half2float(hi));
    g_Bhi[buf * NCOLS * DFEAT + idx] = hi;
    g_Blo[buf * NCOLS * DFEAT + idx] = lo;
}

// ---------------------------------------------------------------------------
// GEMM: 128-row blocks, 8 warps.
// blockIdx.y==4: self tile, 3-term split -> outbuf (fp32)
// blockIdx.y<4 : 4 relation tiles, 1-term -> g_Yh via smem staging;
//                rows with no (src,rel) edge are skipped (dead-message elim)
// ---------------------------------------------------------------------------
#define ASTRIDE 72
#define SM_AHI  0
#define SM_ALO  (128 * ASTRIDE * 2)      // also epilogue staging (128 x 144B)
#define SM_BHI  (SM_ALO + 128 * ASTRIDE * 2)
#define SM_BLO  (SM_BHI + 64 * ASTRIDE * 2)
#define SMEM_BYTES (SM_BLO + 64 * ASTRIDE * 2)   // 55296

__global__ void __launch_bounds__(256) gemm_mma(const float* __restrict__ xres,
                                                const float* __restrict__ bias,
                                                float* __restrict__ outbuf,
                                                int N, int residual, int wbuf) {
    extern __shared__ char smem[];
    const uint32_t sb = smem_to_u32(smem);
    const int t   = threadIdx.x;
    const int wid = t >> 5, lid = t & 31;
    const int n0  = blockIdx.x * 128;
    const bool self_tile = (blockIdx.y == 4);
    const size_t wb0 = (size_t)wbuf * NCOLS * DFEAT;

    // ---- load A tiles ----
    const uint4* XhiV = (const uint4*)g_Xhi;
    const uint4* XloV = (const uint4*)g_Xlo;
#pragma unroll
    for (int i = t; i < 1024; i += 256) {
        int row = i >> 3, q = i & 7;
        int n = n0 + row; if (n >= N) n = N - 1;
        uint32_t d = (uint32_t)(row * ASTRIDE * 2 + q * 16);
        *(uint4*)(smem + SM_AHI + d) = XhiV[(size_t)n * 8 + q];
        if (self_tile)
            *(uint4*)(smem + SM_ALO + d) = XloV[(size_t)n * 8 + q];
    }

    const int wr = wid >> 1;
    const int wc = wid & 1;
    const int sub = lid >> 3;
    const int l7  = lid & 7;
    const int a_row = wr * 32 + ((sub & 1) << 3) + l7;
    const int a_kof = (sub >> 1) << 3;
    const int b_row = wc * 32 + ((sub >> 1) << 3) + l7;
    const int b_kof = (sub & 1) << 3;
    const int g  = lid >> 2;
    const int tg = lid & 3;

    const uint4* BhiV = (const uint4*)(g_Bhi + wb0);
    const uint4* BloV = (const uint4*)(g_Blo + wb0);

    if (self_tile) {
#pragma unroll
        for (int i = t; i < 512; i += 256) {
            int row = i >> 3, q = i & 7;
            uint32_t d = (uint32_t)(row * ASTRIDE * 2 + q * 16);
            *(uint4*)(smem + SM_BHI + d) = BhiV[(size_t)row * 8 + q];
            *(uint4*)(smem + SM_BLO + d) = BloV[(size_t)row * 8 + q];
        }
        __syncthreads();

        float acc[2][4][4];
#pragma unroll
        for (int mi = 0; mi < 2; mi++)
#pragma unroll
            for (int nt = 0; nt < 4; nt++)
#pragma unroll
                for (int q = 0; q < 4; q++) acc[mi][nt][q] = 0.0f;

#pragma unroll
        for (int ks = 0; ks < 4; ks++) {
            const int k0 = ks * 16;
            uint32_t ah[2][4], al[2][4], bh[2][4], bl[2][4];
#pragma unroll
            for (int mi = 0; mi < 2; mi++) {
                uint32_t off = (uint32_t)((a_row + mi * 16) * ASTRIDE + k0 + a_kof) * 2;
                ldsm4(ah[mi], sb + SM_AHI + off);
                ldsm4(al[mi], sb + SM_ALO + off);
            }
#pragma unroll
            for (int nj = 0; nj < 2; nj++) {
                uint32_t off = (uint32_t)((b_row + nj * 16) * ASTRIDE + k0 + b_kof) * 2;
                ldsm4(bh[nj], sb + SM_BHI + off);
                ldsm4(bl[nj], sb + SM_BLO + off);
            }
#pragma unroll
            for (int mi = 0; mi < 2; mi++)
#pragma unroll
                for (int nt = 0; nt < 4; nt++) {
                    const uint32_t* bhp = &bh[nt >> 1][(nt & 1) * 2];
                    mma_fp16(acc[mi][nt], ah[mi], bhp);
                    mma_fp16(acc[mi][nt], ah[mi], &bl[nt >> 1][(nt & 1) * 2]);
                    mma_fp16(acc[mi][nt], al[mi], bhp);
                }
        }

#pragma unroll
        for (int mi = 0; mi < 2; mi++)
#pragma unroll
            for (int hf = 0; hf < 2; hf++) {
                int row = n0 + wr * 32 + mi * 16 + g + hf * 8;
                if (row >= N) continue;
#pragma unroll
                for (int nt = 0; nt < 4; nt++) {
                    int cl = wc * 32 + nt * 8 + tg * 2;
                    float v0 = acc[mi][nt][hf * 2 + 0] + bias[cl];
                    float v1 = acc[mi][nt][hf * 2 + 1] + bias[cl + 1];
                    if (residual) {
                        v0 += xres[(size_t)row * DFEAT + cl];
                        v1 += xres[(size_t)row * DFEAT + cl + 1];
                    }
                    *(float2*)(outbuf + (size_t)row * DFEAT + cl) = make_float2(v0, v1);
                }
            }
        return;
    }

    // ---- 4 relation tiles, 1-term, smem-staged coalesced stores ----
    const int rows_here = min(128, N - n0);

#pragma unroll
    for (int it = 0; it < 4; it++) {
        const int rel = blockIdx.y * 4 + it;
        const int cg0 = (1 + rel) * 64;

        __syncthreads();
#pragma unroll
        for (int i = t; i < 512; i += 256) {
            int row = i >> 3, q = i & 7;
            uint32_t d = (uint32_t)(row * ASTRIDE * 2 + q * 16);
            *(uint4*)(smem + SM_BHI + d) = BhiV[(size_t)(cg0 + row) * 8 + q];
        }
        __syncthreads();

        float acc[2][4][4];
#pragma unroll
        for (int mi = 0; mi < 2; mi++)
#pragma unroll
            for (int nt = 0; nt < 4; nt++)
#pragma unroll
                for (int q = 0; q < 4; q++) acc[mi][nt][q] = 0.0f;

#pragma unroll
        for (int ks = 0; ks < 4; ks++) {
            const int k0 = ks * 16;
            uint32_t ah[2][4], bh[2][4];
#pragma unroll
            for (int mi = 0; mi < 2; mi++) {
                uint32_t off = (uint32_t)((a_row + mi * 16) * ASTRIDE + k0 + a_kof) * 2;
                ldsm4(ah[mi], sb + SM_AHI + off);
            }
#pragma unroll
            for (int nj = 0; nj < 2; nj++) {
                uint32_t off = (uint32_t)((b_row + nj * 16) * ASTRIDE + k0 + b_kof) * 2;
                ldsm4(bh[nj], sb + SM_BHI + off);
            }
#pragma unroll
            for (int mi = 0; mi < 2; mi++)
#pragma unroll
                for (int nt = 0; nt < 4; nt++)
                    mma_fp16(acc[mi][nt], ah[mi], &bh[nt >> 1][(nt & 1) * 2]);
        }

        // stage accumulators to smem (row stride 144 B, conflict-free)
#pragma unroll
        for (int mi = 0; mi < 2; mi++)
#pragma unroll
            for (int hf = 0; hf < 2; hf++) {
                int rl = wr * 32 + mi * 16 + g + hf * 8;
#pragma unroll
                for (int nt = 0; nt < 4; nt++) {
                    int cl = wc * 32 + nt * 8 + tg * 2;
                    __half2 hv = __floats2half2_rn(acc[mi][nt][hf * 2 + 0],
                                                   acc[mi][nt][hf * 2 + 1]);
                    *(uint32_t*)(smem + SM_ALO + rl * (ASTRIDE * 2) + cl * 2) =
                        *(uint32_t*)&hv;
                }
            }
        __syncthreads();

        // coalesced store: 128 rows x 128 B, skipping rows with no (src,rel) edge
        __half* ybase = g_Yh + (size_t)rel * 64;
        const uint8_t* um = g_used + (size_t)rel * N + n0;
#pragma unroll
        for (int j = 0; j < 4; j++) {
            int i = t + j * 256;
            int row = i >> 3, q = i & 7;
            if (row < rows_here && um[row]) {
                uint4 v = *(uint4*)(smem + SM_ALO + row * (ASTRIDE * 2) + q * 16);
                *(uint4*)(ybase + (size_t)(n0 + row) * RELCOLS + q * 8) = v;
            }
        }
    }
}

// ---------------------------------------------------------------------------
// CSR aggregation. to_x=1: relu result -> fp16 hi/lo operand; else fp32 inout.
// ---------------------------------------------------------------------------
__global__ void __launch_bounds__(256) agg_k(float* __restrict__ inout, int N, int to_x) {
    const int wid  = threadIdx.x >> 5;
    const int lid  = threadIdx.x & 31;
    const int node = blockIdx.x * 8 + wid;
    if (node >= N) return;

    const int s  = g_indptr[node];
    const int e2 = g_indptr[node + 1];

    float ax = 0.0f, ay = 0.0f;
    const __half* Yh = g_Yh;
    const int co = lid * 2;

    int i = s;
    for (; i + 3 < e2; i += 4) {
        uint32_t p0 = g_edata[i],     p1 = g_edata[i + 1];
        uint32_t p2 = g_edata[i + 2], p3 = g_edata[i + 3];
        __half2 v0 = *(const __half2*)(Yh + (size_t)(p0 & 0xFFFFF) * RELCOLS + ((p0 >> 20) << 6) + co);
        __half2 v1 = *(const __half2*)(Yh + (size_t)(p1 & 0xFFFFF) * RELCOLS + ((p1 >> 20) << 6) + co);
        __half2 v2 = *(const __half2*)(Yh + (size_t)(p2 & 0xFFFFF) * RELCOLS + ((p2 >> 20) << 6) + co);
        __half2 v3 = *(const __half2*)(Yh + (size_t)(p3 & 0xFFFFF) * RELCOLS + ((p3 >> 20) << 6) + co);
        float2 f0 = __half22float2(v0), f1 = __half22float2(v1);
        float2 f2 = __half22float2(v2), f3 = __half22float2(v3);
        ax += (f0.x + f1.x) + (f2.x + f3.x);
        ay += (f0.y + f1.y) + (f2.y + f3.y);
    }
    for (; i < e2; i++) {
        uint32_t p0 = g_edata[i];
        __half2 v0 = *(const __half2*)(Yh + (size_t)(p0 & 0xFFFFF) * RELCOLS + ((p0 >> 20) << 6) + co);
        float2 f0 = __half22float2(v0);
        ax += f0.x;
        ay += f0.y;
    }

    float* p = inout + (size_t)node * DFEAT + co;
    float2 base = *(float2*)p;
    float rx = fmaxf(base.x + ax, 0.0f);
    float ry = fmaxf(base.y + ay, 0.0f);
    if (to_x) {
        __half h0 = __float2half_rn(rx);
        __half h1 = __float2half_rn(ry);
        __half l0 = __float2half_rn(rx - __half2float(h0));
        __half l1 = __float2half_rn(ry - __half2float(h1));
        __half2 hh = __halves2half2(h0, h1);
        __half2 ll = __halves2half2(l0, l1);
        *(uint32_t*)(g_Xhi + (size_t)node * DFEAT + co) = *(uint32_t*)&hh;
        *(uint32_t*)(g_Xlo + (size_t)node * DFEAT + co) = *(uint32_t*)&ll;
    } else {
        *(float2*)p = make_float2(rx, ry);
    }
}

// ---------------------------------------------------------------------------
extern "C" void kernel_launch(void* const* d_in, const int* in_sizes, int n_in,
                              void* d_out, int out_size) {
    const float* x   = (const float*)d_in[0];
    const int*   ei  = (const int*)d_in[1];
    const int*   et  = (const int*)d_in[2];
    const float* W1  = (const float*)d_in[3];
    const float* sw1 = (const float*)d_in[4];
    const float* b1  = (const float*)d_in[5];
    const float* W2  = (const float*)d_in[6];
    const float* sw2 = (const float*)d_in[7];
    const float* b2  = (const float*)d_in[8];
    float* out = (float*)d_out;

    const int N = in_sizes[0] / DFEAT;
    const int E = in_sizes[2];
    const int total4 = N * (DFEAT / 4);
    const int nb = (N + 1023) / 1024;

    float* hptr = nullptr;
    cudaGetSymbolAddress((void**)&hptr, g_h);
    int* cntptr = nullptr;
    cudaGetSymbolAddress((void**)&cntptr, g_cnt);
    uint8_t* usedptr = nullptr;
    cudaGetSymbolAddress((void**)&usedptr, g_used);

    static cudaStream_t s1 = nullptr;
    static cudaEvent_t ev_fork = nullptr, ev_join = nullptr, ev_used = nullptr;
    if (!s1) {
        cudaStreamCreateWithFlags(&s1, cudaStreamNonBlocking);
        cudaEventCreateWithFlags(&ev_fork, cudaEventDisableTiming);
        cudaEventCreateWithFlags(&ev_join, cudaEventDisableTiming);
        cudaEventCreateWithFlags(&ev_used, cudaEventDisableTiming);
    }

    cudaFuncSetAttribute(gemm_mma, cudaFuncAttributeMaxDynamicSharedMemorySize, SMEM_BYTES);

    dim3 gemm_grid((N + 127) / 128, 5);   // y: 0..3 = 4 rels each, 4 = self
    int pack_blocks = (NCOLS * DFEAT + 255) / 256;
    int el_blocks   = (total4 + 255) / 256;
    int e_blocks    = (E + 255) / 256;
    int agg_blocks  = (N + 7) / 8;

    // ---- fork: used-map, CSR build, layer-2 weight pack on side stream ----
    cudaEventRecord(ev_fork, 0);
    cudaStreamWaitEvent(s1, ev_fork, 0);
    cudaMemsetAsync(usedptr, 0, (size_t)NREL * N, s1);
    mark_k<<<e_blocks, 256, 0, s1>>>(ei, et, E, N);
    cudaEventRecord(ev_used, s1);
    cudaMemsetAsync(cntptr, 0, (size_t)N * sizeof(int), s1);
    hist_k<<<e_blocks, 256, 0, s1>>>(ei, E);
    scan1<<<nb, 1024, 0, s1>>>(N);
    scan2<<<1, NBLK_MAX, 0, s1>>>(nb);
    scan3<<<nb, 1024, 0, s1>>>(N, E);
    fill_k<<<e_blocks, 256, 0, s1>>>(ei, et, E);
    pack_wb<<<pack_blocks, 256, 0, s1>>>(W2, sw2, 1);
    cudaEventRecord(ev_join, s1);

    // ---- main stream: layer 1 ----
    conv_fp16<<<el_blocks, 256>>>(x, total4);
    pack_wb<<<pack_blocks, 256>>>(W1, sw1, 0);
    cudaStreamWaitEvent(0, ev_used, 0);   // used-map ready for gemm store mask
    gemm_mma<<<gemm_grid, 256, SMEM_BYTES>>>(x, b1, hptr, N, 1, 0);
    cudaStreamWaitEvent(0, ev_join, 0);   // CSR + pack2 ready
    agg_k<<<agg_blocks, 256>>>(hptr, N, 1);

    // ---- layer 2 ----
    gemm_mma<<<gemm_grid, 256, SMEM_BYTES>>>(x, b2, out, N, 0, 1);
    agg_k<<<agg_blocks, 256>>>(out, N, 0);
}

// round 15
// speedup vs baseline: 1.2118x; 1.2118x over previous
#include <cuda_runtime.h>
#include <cuda_fp16.h>
#include <cstdint>

#define DFEAT 64
#define NREL 16
#define NCOLS 1088           // (NREL+1)*64
#define RELCOLS 1024         // NREL*64 halves per Yh row
#define NNODE_MAX 100000
#define EDGE_MAX  1500000
#define NBLK_MAX  128

typedef unsigned long long u64;

// ---------------------------------------------------------------------------
// Scratch (allocation-free, __device__ globals)
// ---------------------------------------------------------------------------
__device__ __half  g_Yh[(size_t)NNODE_MAX * RELCOLS];  // ~205 MB fp16 messages
__device__ float   g_h[(size_t)NNODE_MAX * DFEAT];
__device__ __half  g_Xhi[(size_t)NNODE_MAX * DFEAT];
__device__ __half  g_Xlo[(size_t)NNODE_MAX * DFEAT];
__device__ __half  g_Bhi[2 * NCOLS * DFEAT];           // double-buffered (layer 1/2)
__device__ __half  g_Blo[2 * NCOLS * DFEAT];
// CSR
__device__ int      g_cnt[NNODE_MAX];
__device__ int      g_indptr[NNODE_MAX + 1];
__device__ int      g_cursor[NNODE_MAX];
__device__ int      g_bsum[NBLK_MAX];
__device__ uint32_t g_edata[EDGE_MAX];   // src | ty<<20

// ---------------------------------------------------------------------------
__device__ __forceinline__ uint32_t smem_to_u32(const void* p) {
    uint32_t a;
    asm("{ .reg .u64 t; cvta.to.shared.u64 t, %1; cvt.u32.u64 %0, t; }" : "=r"(a) : "l"(p));
    return a;
}
__device__ __forceinline__ void ldsm4(uint32_t* r, uint32_t a) {
    asm volatile("ldmatrix.sync.aligned.m8n8.x4.shared.b16 {%0,%1,%2,%3}, [%4];"
                 : "=r"(r[0]), "=r"(r[1]), "=r"(r[2]), "=r"(r[3]) : "r"(a));
}
__device__ __forceinline__ void mma_fp16(float* d, const uint32_t* a, const uint32_t* b) {
    asm volatile("mma.sync.aligned.m16n8k16.row.col.f32.f16.f16.f32 "
                 "{%0,%1,%2,%3}, {%4,%5,%6,%7}, {%8,%9}, {%0,%1,%2,%3};"
                 : "+f"(d[0]), "+f"(d[1]), "+f"(d[2]), "+f"(d[3])
                 : "r"(a[0]), "r"(a[1]), "r"(a[2]), "r"(a[3]), "r"(b[0]), "r"(b[1]));
}

// ---------------------------------------------------------------------------
// CSR build kernels
// ---------------------------------------------------------------------------
__global__ void hist_k(const int* __restrict__ ei, int E) {
    int e = blockIdx.x * blockDim.x + threadIdx.x;
    if (e >= E) return;
    atomicAdd(&g_cnt[ei[E + e]], 1);
}
__global__ void scan1(int N) {
    __shared__ int sh[1024];
    int gid = blockIdx.x * 1024 + threadIdx.x;
    int v = (gid < N) ? g_cnt[gid] : 0;
    sh[threadIdx.x] = v;
    __syncthreads();
    for (int off = 1; off < 1024; off <<= 1) {
        int t = (threadIdx.x >= off) ? sh[threadIdx.x - off] : 0;
        __syncthreads();
        sh[threadIdx.x] += t;
        __syncthreads();
    }
    if (gid < N) g_indptr[gid] = sh[threadIdx.x] - v;
    if (threadIdx.x == 1023) g_bsum[blockIdx.x] = sh[1023];
}
__global__ void scan2(int nb) {
    __shared__ int sh[NBLK_MAX];
    int t = threadIdx.x;
    int v = (t < nb) ? g_bsum[t] : 0;
    sh[t] = v;
    __syncthreads();
    for (int off = 1; off < NBLK_MAX; off <<= 1) {
        int a = (t >= off) ? sh[t - off] : 0;
        __syncthreads();
        sh[t] += a;
        __syncthreads();
    }
    if (t < nb) g_bsum[t] = sh[t] - v;
}
__global__ void scan3(int N, int E) {
    int gid = blockIdx.x * 1024 + threadIdx.x;
    if (gid < N) {
        int v = g_indptr[gid] + g_bsum[blockIdx.x];
        g_indptr[gid] = v;
        g_cursor[gid] = v;
    }
    if (gid == 0) g_indptr[N] = E;
}
__global__ void fill_k(const int* __restrict__ ei, const int* __restrict__ et, int E) {
    int e = blockIdx.x * blockDim.x + threadIdx.x;
    if (e >= E) return;
    int src = ei[e];
    int dst = ei[E + e];
    int ty  = et[e];
    int pos = atomicAdd(&g_cursor[dst], 1);
    g_edata[pos] = (uint32_t)src | ((uint32_t)ty << 20);
}

// ---------------------------------------------------------------------------
// fp16 hi/lo conversion (layer-1 input only)
// ---------------------------------------------------------------------------
__global__ void conv_fp16(const float* __restrict__ src, int total4) {
    int idx4 = blockIdx.x * blockDim.x + threadIdx.x;
    if (idx4 >= total4) return;
    float4 v = *(const float4*)(src + (size_t)idx4 * 4);
    float f[4] = {v.x, v.y, v.z, v.w};
    union { __half b[4]; uint2 u; } hi, lo;
#pragma unroll
    for (int i = 0; i < 4; i++) {
        hi.b[i] = __float2half_rn(f[i]);
        lo.b[i] = __float2half_rn(f[i] - __half2float(hi.b[i]));
    }
    *(uint2*)(g_Xhi + (size_t)idx4 * 4) = hi.u;
    *(uint2*)(g_Xlo + (size_t)idx4 * 4) = lo.u;
}

// ---------------------------------------------------------------------------
// Pack B[c][k] = Wcat[k][c] (fp16 hi/lo) into buffer `buf`
// ---------------------------------------------------------------------------
__global__ void pack_wb(const float* __restrict__ W, const float* __restrict__ sw, int buf) {
    int idx = blockIdx.x * blockDim.x + threadIdx.x;
    if (idx >= NCOLS * DFEAT) return;
    int c = idx / DFEAT;
    int k = idx - c * DFEAT;
    float v;
    if (c < DFEAT) {
        v = sw[k * DFEAT + c];
    } else {
        int rc = c - DFEAT;
        int r = rc >> 6, j = rc & 63;
        v = W[r * DFEAT * DFEAT + k * DFEAT + j];
    }
    __half hi = __float2half_rn(v);
    __half lo = __float2half_rn(v - __half2float(hi));
    g_Bhi[buf * NCOLS * DFEAT + idx] = hi;
    g_Blo[buf * NCOLS * DFEAT + idx] = lo;
}

// ---------------------------------------------------------------------------
// GEMM: 128-row blocks, 8 warps.
// blockIdx.y==4: self tile, 3-term split -> outbuf (fp32)
// blockIdx.y<4 : 4 relation tiles, 1-term -> g_Yh via smem staging
// ---------------------------------------------------------------------------
#define ASTRIDE 72
#define SM_AHI  0
#define SM_ALO  (128 * ASTRIDE * 2)      // also epilogue staging (128 x 144B)
#define SM_BHI  (SM_ALO + 128 * ASTRIDE * 2)
#define SM_BLO  (SM_BHI + 64 * ASTRIDE * 2)
#define SMEM_BYTES (SM_BLO + 64 * ASTRIDE * 2)   // 55296

__global__ void __launch_bounds__(256) gemm_mma(const float* __restrict__ xres,
                                                const float* __restrict__ bias,
                                                float* __restrict__ outbuf,
                                                int N, int residual, int wbuf) {
    extern __shared__ char smem[];
    const uint32_t sb = smem_to_u32(smem);
    const int t   = threadIdx.x;
    const int wid = t >> 5, lid = t & 31;
    const int n0  = blockIdx.x * 128;
    const bool self_tile = (blockIdx.y == 4);
    const size_t wb0 = (size_t)wbuf * NCOLS * DFEAT;

    // ---- load A tiles ----
    const uint4* XhiV = (const uint4*)g_Xhi;
    const uint4* XloV = (const uint4*)g_Xlo;
#pragma unroll
    for (int i = t; i < 1024; i += 256) {
        int row = i >> 3, q = i & 7;
        int n = n0 + row; if (n >= N) n = N - 1;
        uint32_t d = (uint32_t)(row * ASTRIDE * 2 + q * 16);
        *(uint4*)(smem + SM_AHI + d) = XhiV[(size_t)n * 8 + q];
        if (self_tile)
            *(uint4*)(smem + SM_ALO + d) = XloV[(size_t)n * 8 + q];
    }

    const int wr = wid >> 1;
    const int wc = wid & 1;
    const int sub = lid >> 3;
    const int l7  = lid & 7;
    const int a_row = wr * 32 + ((sub & 1) << 3) + l7;
    const int a_kof = (sub >> 1) << 3;
    const int b_row = wc * 32 + ((sub >> 1) << 3) + l7;
    const int b_kof = (sub & 1) << 3;
    const int g  = lid >> 2;
    const int tg = lid & 3;

    const uint4* BhiV = (const uint4*)(g_Bhi + wb0);
    const uint4* BloV = (const uint4*)(g_Blo + wb0);

    if (self_tile) {
#pragma unroll
        for (int i = t; i < 512; i += 256) {
            int row = i >> 3, q = i & 7;
            uint32_t d = (uint32_t)(row * ASTRIDE * 2 + q * 16);
            *(uint4*)(smem + SM_BHI + d) = BhiV[(size_t)row * 8 + q];
            *(uint4*)(smem + SM_BLO + d) = BloV[(size_t)row * 8 + q];
        }
        __syncthreads();

        float acc[2][4][4];
#pragma unroll
        for (int mi = 0; mi < 2; mi++)
#pragma unroll
            for (int nt = 0; nt < 4; nt++)
#pragma unroll
                for (int q = 0; q < 4; q++) acc[mi][nt][q] = 0.0f;

#pragma unroll
        for (int ks = 0; ks < 4; ks++) {
            const int k0 = ks * 16;
            uint32_t ah[2][4], al[2][4], bh[2][4], bl[2][4];
#pragma unroll
            for (int mi = 0; mi < 2; mi++) {
                uint32_t off = (uint32_t)((a_row + mi * 16) * ASTRIDE + k0 + a_kof) * 2;
                ldsm4(ah[mi], sb + SM_AHI + off);
                ldsm4(al[mi], sb + SM_ALO + off);
            }
#pragma unroll
            for (int nj = 0; nj < 2; nj++) {
                uint32_t off = (uint32_t)((b_row + nj * 16) * ASTRIDE + k0 + b_kof) * 2;
                ldsm4(bh[nj], sb + SM_BHI + off);
                ldsm4(bl[nj], sb + SM_BLO + off);
            }
#pragma unroll
            for (int mi = 0; mi < 2; mi++)
#pragma unroll
                for (int nt = 0; nt < 4; nt++) {
                    const uint32_t* bhp = &bh[nt >> 1][(nt & 1) * 2];
                    mma_fp16(acc[mi][nt], ah[mi], bhp);
                    mma_fp16(acc[mi][nt], ah[mi], &bl[nt >> 1][(nt & 1) * 2]);
                    mma_fp16(acc[mi][nt], al[mi], bhp);
                }
        }

#pragma unroll
        for (int mi = 0; mi < 2; mi++)
#pragma unroll
            for (int hf = 0; hf < 2; hf++) {
                int row = n0 + wr * 32 + mi * 16 + g + hf * 8;
                if (row >= N) continue;
#pragma unroll
                for (int nt = 0; nt < 4; nt++) {
                    int cl = wc * 32 + nt * 8 + tg * 2;
                    float v0 = acc[mi][nt][hf * 2 + 0] + bias[cl];
                    float v1 = acc[mi][nt][hf * 2 + 1] + bias[cl + 1];
                    if (residual) {
                        v0 += xres[(size_t)row * DFEAT + cl];
                        v1 += xres[(size_t)row * DFEAT + cl + 1];
                    }
                    *(float2*)(outbuf + (size_t)row * DFEAT + cl) = make_float2(v0, v1);
                }
            }
        return;
    }

    // ---- 4 relation tiles, 1-term, smem-staged coalesced stores ----
    const int rows_here = min(128, N - n0);

#pragma unroll
    for (int it = 0; it < 4; it++) {
        const int rel = blockIdx.y * 4 + it;
        const int cg0 = (1 + rel) * 64;

        __syncthreads();
#pragma unroll
        for (int i = t; i < 512; i += 256) {
            int row = i >> 3, q = i & 7;
            uint32_t d = (uint32_t)(row * ASTRIDE * 2 + q * 16);
            *(uint4*)(smem + SM_BHI + d) = BhiV[(size_t)(cg0 + row) * 8 + q];
        }
        __syncthreads();

        float acc[2][4][4];
#pragma unroll
        for (int mi = 0; mi < 2; mi++)
#pragma unroll
            for (int nt = 0; nt < 4; nt++)
#pragma unroll
                for (int q = 0; q < 4; q++) acc[mi][nt][q] = 0.0f;

#pragma unroll
        for (int ks = 0; ks < 4; ks++) {
            const int k0 = ks * 16;
            uint32_t ah[2][4], bh[2][4];
#pragma unroll
            for (int mi = 0; mi < 2; mi++) {
                uint32_t off = (uint32_t)((a_row + mi * 16) * ASTRIDE + k0 + a_kof) * 2;
                ldsm4(ah[mi], sb + SM_AHI + off);
            }
#pragma unroll
            for (int nj = 0; nj < 2; nj++) {
                uint32_t off = (uint32_t)((b_row + nj * 16) * ASTRIDE + k0 + b_kof) * 2;
                ldsm4(bh[nj], sb + SM_BHI + off);
            }
#pragma unroll
            for (int mi = 0; mi < 2; mi++)
#pragma unroll
                for (int nt = 0; nt < 4; nt++)
                    mma_fp16(acc[mi][nt], ah[mi], &bh[nt >> 1][(nt & 1) * 2]);
        }

        // stage accumulators to smem (row stride 144 B, conflict-free)
#pragma unroll
        for (int mi = 0; mi < 2; mi++)
#pragma unroll
            for (int hf = 0; hf < 2; hf++) {
                int rl = wr * 32 + mi * 16 + g + hf * 8;
#pragma unroll
                for (int nt = 0; nt < 4; nt++) {
                    int cl = wc * 32 + nt * 8 + tg * 2;
                    __half2 hv = __floats2half2_rn(acc[mi][nt][hf * 2 + 0],
                                                   acc[mi][nt][hf * 2 + 1]);
                    *(uint32_t*)(smem + SM_ALO + rl * (ASTRIDE * 2) + cl * 2) =
                        *(uint32_t*)&hv;
                }
            }
        __syncthreads();

        // coalesced store: 128 rows x 128 B
        __half* ybase = g_Yh + (size_t)rel * 64;
#pragma unroll
        for (int j = 0; j < 4; j++) {
            int i = t + j * 256;
            int row = i >> 3, q = i & 7;
            if (row < rows_here) {
                uint4 v = *(uint4*)(smem + SM_ALO + row * (ASTRIDE * 2) + q * 16);
                *(uint4*)(ybase + (size_t)(n0 + row) * RELCOLS + q * 8) = v;
            }
        }
    }
}

// ---------------------------------------------------------------------------
// CSR aggregation. to_x=1: relu result -> fp16 hi/lo operand; else fp32 inout.
// ---------------------------------------------------------------------------
__global__ void __launch_bounds__(256) agg_k(float* __restrict__ inout, int N, int to_x) {
    const int wid  = threadIdx.x >> 5;
    const int lid  = threadIdx.x & 31;
    const int node = blockIdx.x * 8 + wid;
    if (node >= N) return;

    const int s  = g_indptr[node];
    const int e2 = g_indptr[node + 1];

    float ax = 0.0f, ay = 0.0f;
    const __half* Yh = g_Yh;
    const int co = lid * 2;

    int i = s;
    for (; i + 3 < e2; i += 4) {
        uint32_t p0 = g_edata[i],     p1 = g_edata[i + 1];
        uint32_t p2 = g_edata[i + 2], p3 = g_edata[i + 3];
        __half2 v0 = *(const __half2*)(Yh + (size_t)(p0 & 0xFFFFF) * RELCOLS + ((p0 >> 20) << 6) + co);
        __half2 v1 = *(const __half2*)(Yh + (size_t)(p1 & 0xFFFFF) * RELCOLS + ((p1 >> 20) << 6) + co);
        __half2 v2 = *(const __half2*)(Yh + (size_t)(p2 & 0xFFFFF) * RELCOLS + ((p2 >> 20) << 6) + co);
        __half2 v3 = *(const __half2*)(Yh + (size_t)(p3 & 0xFFFFF) * RELCOLS + ((p3 >> 20) << 6) + co);
        float2 f0 = __half22float2(v0), f1 = __half22float2(v1);
        float2 f2 = __half22float2(v2), f3 = __half22float2(v3);
        ax += (f0.x + f1.x) + (f2.x + f3.x);
        ay += (f0.y + f1.y) + (f2.y + f3.y);
    }
    for (; i < e2; i++) {
        uint32_t p0 = g_edata[i];
        __half2 v0 = *(const __half2*)(Yh + (size_t)(p0 & 0xFFFFF) * RELCOLS + ((p0 >> 20) << 6) + co);
        float2 f0 = __half22float2(v0);
        ax += f0.x;
        ay += f0.y;
    }

    float* p = inout + (size_t)node * DFEAT + co;
    float2 base = *(float2*)p;
    float rx = fmaxf(base.x + ax, 0.0f);
    float ry = fmaxf(base.y + ay, 0.0f);
    if (to_x) {
        __half h0 = __float2half_rn(rx);
        __half h1 = __float2half_rn(ry);
        __half l0 = __float2half_rn(rx - __half2float(h0));
        __half l1 = __float2half_rn(ry - __half2float(h1));
        __half2 hh = __halves2half2(h0, h1);
        __half2 ll = __halves2half2(l0, l1);
        *(uint32_t*)(g_Xhi + (size_t)node * DFEAT + co) = *(uint32_t*)&hh;
        *(uint32_t*)(g_Xlo + (size_t)node * DFEAT + co) = *(uint32_t*)&ll;
    } else {
        *(float2*)p = make_float2(rx, ry);
    }
}

// ---------------------------------------------------------------------------
extern "C" void kernel_launch(void* const* d_in, const int* in_sizes, int n_in,
                              void* d_out, int out_size) {
    const float* x   = (const float*)d_in[0];
    const int*   ei  = (const int*)d_in[1];
    const int*   et  = (const int*)d_in[2];
    const float* W1  = (const float*)d_in[3];
    const float* sw1 = (const float*)d_in[4];
    const float* b1  = (const float*)d_in[5];
    const float* W2  = (const float*)d_in[6];
    const float* sw2 = (const float*)d_in[7];
    const float* b2  = (const float*)d_in[8];
    float* out = (float*)d_out;

    const int N = in_sizes[0] / DFEAT;
    const int E = in_sizes[2];
    const int total4 = N * (DFEAT / 4);
    const int nb = (N + 1023) / 1024;

    float* hptr = nullptr;
    cudaGetSymbolAddress((void**)&hptr, g_h);
    int* cntptr = nullptr;
    cudaGetSymbolAddress((void**)&cntptr, g_cnt);

    static cudaStream_t s1 = nullptr, s2 = nullptr;
    static cudaEvent_t ev_fork = nullptr, ev_join = nullptr, ev_conv = nullptr;
    if (!s1) {
        cudaStreamCreateWithFlags(&s1, cudaStreamNonBlocking);
        cudaStreamCreateWithFlags(&s2, cudaStreamNonBlocking);
        cudaEventCreateWithFlags(&ev_fork, cudaEventDisableTiming);
        cudaEventCreateWithFlags(&ev_join, cudaEventDisableTiming);
        cudaEventCreateWithFlags(&ev_conv, cudaEventDisableTiming);
    }

    cudaFuncSetAttribute(gemm_mma, cudaFuncAttributeMaxDynamicSharedMemorySize, SMEM_BYTES);

    dim3 gemm_grid((N + 127) / 128, 5);   // y: 0..3 = 4 rels each, 4 = self
    int pack_blocks = (NCOLS * DFEAT + 255) / 256;
    int el_blocks   = (total4 + 255) / 256;
    int e_blocks    = (E + 255) / 256;
    int agg_blocks  = (N + 7) / 8;

    // ---- fork ----
    cudaEventRecord(ev_fork, 0);
    cudaStreamWaitEvent(s1, ev_fork, 0);
    cudaStreamWaitEvent(s2, ev_fork, 0);

    // side stream s1: CSR build + layer-2 weight pack
    cudaMemsetAsync(cntptr, 0, (size_t)N * sizeof(int), s1);
    hist_k<<<e_blocks, 256, 0, s1>>>(ei, E);
    scan1<<<nb, 1024, 0, s1>>>(N);
    scan2<<<1, NBLK_MAX, 0, s1>>>(nb);
    scan3<<<nb, 1024, 0, s1>>>(N, E);
    fill_k<<<e_blocks, 256, 0, s1>>>(ei, et, E);
    pack_wb<<<pack_blocks, 256, 0, s1>>>(W2, sw2, 1);
    cudaEventRecord(ev_join, s1);

    // side stream s2: activation conversion (independent of pack1/CSR)
    conv_fp16<<<el_blocks, 256, 0, s2>>>(x, total4);
    cudaEventRecord(ev_conv, s2);

    // ---- main stream: layer 1 ----
    pack_wb<<<pack_blocks, 256>>>(W1, sw1, 0);
    cudaStreamWaitEvent(0, ev_conv, 0);   // Xhi/Xlo ready
    gemm_mma<<<gemm_grid, 256, SMEM_BYTES>>>(x, b1, hptr, N, 1, 0);
    cudaStreamWaitEvent(0, ev_join, 0);   // CSR + pack2 ready
    agg_k<<<agg_blocks, 256>>>(hptr, N, 1);

    // ---- layer 2 ----
    gemm_mma<<<gemm_grid, 256, SMEM_BYTES>>>(x, b2, out, N, 0, 1);
    agg_k<<<agg_blocks, 256>>>(out, N, 0);
}